// round 13
// baseline (speedup 1.0000x reference)
#include <cuda_runtime.h>

// SoftDTW forward, B=128, N=M=512, gamma=1.
// S = exp(-R):  S[i][j] = exp(-D[i][j]) * (S[i-1][j-1] + S[i-1][j] + S[i][j-1])
// Final: R = -(ln S + Es*ln2), joint (both-warp) power-of-2 rescaling every 5 phases.
//
// One CTA per batch, 5 warps, TWO consumer warps (column split) + 3 producers:
//   consumer C (warp 3+C) owns cols [256C, 256C+256); lane l owns 8 cols.
//   Step s: lane l of consumer C processes row-pair rp = s - 32C - l. 319 steps.
//   Boundary col 255->256 crosses warps via a 64-entry smem mailbox:
//   warp3 lane31 publishes {o,m,h,tag} (one st.volatile.v4) per step; warp4
//   lane0 polls (writer is 1 step ahead -> first poll succeeds).
//   producers (warps 0-2): stream D, exp(-D) into two smem rings:
//   region0 (RS=44) for consumer0 written at phase t+1; region1 (RS=45) written
//   4 phases late (covers consumer1's 32-step lag). Slot (rp+l)%RS.
//   Rescale: joint max via smem + second per-phase barrier; the mailbox entry
//   crossing a rescale boundary is corrected by the last factor.

namespace {
constexpr int BATCH  = 128;
constexpr int NR     = 512;
constexpr int MC     = 512;
constexpr int NRP    = 256;                    // row pairs
constexpr int KP     = 6;                      // steps per phase
constexpr int RS0    = 44;
constexpr int RS1    = 45;
constexpr int LS     = 20;                     // words per lane chunk (16 + pad, 16B-aligned)
constexpr int SLOTW  = 32 * LS;                // 640 words per slot
constexpr int SMEM_BYTES = (RS0 + RS1) * SLOTW * 4;   // 227840
constexpr int STEPS  = NRP + 63;               // 319
constexpr int NPHASE = 54;                     // even; covers 324 steps
constexpr unsigned FULL = 0xffffffffu;
}

__device__ __forceinline__ float4 exp4neg(float4 v) {
    float4 r;
    r.x = __expf(-v.x); r.y = __expf(-v.y);
    r.z = __expf(-v.z); r.w = __expf(-v.w);
    return r;
}
__device__ __forceinline__ void sts128v(unsigned a, float x, float y, float z, float w) {
    asm volatile("st.volatile.shared.v4.f32 [%0], {%1,%2,%3,%4};"
                 :: "r"(a), "f"(x), "f"(y), "f"(z), "f"(w));
}
__device__ __forceinline__ float4 lds128v(unsigned a) {
    float4 v;
    asm volatile("ld.volatile.shared.v4.f32 {%0,%1,%2,%3}, [%4];"
                 : "=f"(v.x), "=f"(v.y), "=f"(v.z), "=f"(v.w) : "r"(a));
    return v;
}

// ---------------- consumer ----------------
template <int C>
__device__ __forceinline__ void consumer_loop(
    const float* __restrict__ region, float* __restrict__ out, int b, int l,
    unsigned mb, volatile float* jm)
{
    float h[8];
    #pragma unroll
    for (int j = 0; j < 8; ++j) h[j] = 0.f;
    float o7 = 0.f, m7 = 0.f;          // boundary history (cols +7): rows 2rp-1, 2rp
    int   Es = 0;
    float f_last = 1.f;
    constexpr int RSC  = 44 + C;
    constexpr int BASE = 32 * C;
    const float* lane_base = region + l * LS;

    for (int t = 0; t < NPHASE; ++t) {
        __syncthreads();
        const bool steady = (t >= 6 + 5 * C) && (t <= 41 + 6 * C);
        if (steady) {
            int slot = (6 * t - BASE) % RSC;
            #pragma unroll
            for (int q = 0; q < KP; ++q) {
                const int s = 6 * t + q;
                const float4* e4 = (const float4*)(lane_base + slot * SLOTW);
                const float4 A0 = e4[0], A1 = e4[1], B0 = e4[2], B1 = e4[3];
                const float y0 = __shfl_up_sync(FULL, o7,  1);
                const float y1 = __shfl_up_sync(FULL, m7,  1);
                const float y2 = __shfl_up_sync(FULL, h[7], 1);
                float z0, z1, z2;
                if (C == 1) {
                    const int rp0 = s - 32;
                    const unsigned a = mb + (unsigned)((rp0 & 63) * 16);
                    float4 v = lds128v(a);
                    while (__float_as_int(v.w) != rp0) v = lds128v(a);
                    const float corr = (q == 0 && (t % 5) == 0) ? f_last : 1.f;
                    z0 = (l == 0) ? v.x * corr : y0;
                    z1 = (l == 0) ? v.y * corr : y1;
                    z2 = (l == 0) ? v.z * corr : y2;
                } else {
                    z0 = (l == 0) ? 0.f : y0;
                    z1 = (l == 0) ? 0.f : y1;
                    z2 = (l == 0) ? 0.f : y2;
                }
                const float ea[8] = { A0.x, A0.y, A0.z, A0.w, A1.x, A1.y, A1.z, A1.w };
                const float eb[8] = { B0.x, B0.y, B0.z, B0.w, B1.x, B1.y, B1.z, B1.w };
                float pa[8];
                pa[0] = ea[0] * (z0 + h[0]);
                #pragma unroll
                for (int j = 1; j < 8; ++j) pa[j] = ea[j] * (h[j - 1] + h[j]);
                float av[8];
                float c = z1;
                #pragma unroll
                for (int j = 0; j < 8; ++j) { c = fmaf(ea[j], c, pa[j]); av[j] = c; }
                float pb[8];
                pb[0] = eb[0] * (z1 + av[0]);
                #pragma unroll
                for (int j = 1; j < 8; ++j) pb[j] = eb[j] * (av[j - 1] + av[j]);
                const float o7n = h[7];
                float d = z2;
                #pragma unroll
                for (int j = 0; j < 8; ++j) { d = fmaf(eb[j], d, pb[j]); h[j] = d; }
                o7 = o7n; m7 = av[7];
                if (C == 0 && l == 31)
                    sts128v(mb + (unsigned)(((s - 31) & 63) * 16),
                            o7, m7, h[7], __int_as_float(s - 31));
                slot = (slot + 1 == RSC) ? 0 : slot + 1;
            }
        } else {
            #pragma unroll
            for (int q = 0; q < KP; ++q) {
                const int s = 6 * t + q;
                if (s < STEPS) {
                    const int u = s - BASE;            // warp-uniform
                    if (u >= 0) {
                        const int slot = u % RSC;
                        const float4* e4 = (const float4*)(lane_base + slot * SLOTW);
                        const float4 A0 = e4[0], A1 = e4[1], B0 = e4[2], B1 = e4[3];
                        const float y0 = __shfl_up_sync(FULL, o7,  1);
                        const float y1 = __shfl_up_sync(FULL, m7,  1);
                        const float y2 = __shfl_up_sync(FULL, h[7], 1);
                        float z0, z1, z2;
                        if (C == 1) {
                            float4 v = make_float4(0.f, 0.f, 0.f, 0.f);
                            if (u < NRP) {
                                const unsigned a = mb + (unsigned)((u & 63) * 16);
                                v = lds128v(a);
                                while (__float_as_int(v.w) != u) v = lds128v(a);
                            }
                            const float corr = (q == 0 && (t % 5) == 0) ? f_last : 1.f;
                            z0 = (l == 0) ? v.x * corr : y0;
                            z1 = (l == 0) ? v.y * corr : y1;
                            z2 = (l == 0) ? v.z * corr : y2;
                        } else {
                            z0 = (l == 0) ? ((s == 0) ? 1.f : 0.f) : y0;  // corner S[-1][-1]=1
                            z1 = (l == 0) ? 0.f : y1;
                            z2 = (l == 0) ? 0.f : y2;
                        }
                        const bool act = (unsigned)(u - l) < (unsigned)NRP;
                        const float ea[8] = { A0.x, A0.y, A0.z, A0.w, A1.x, A1.y, A1.z, A1.w };
                        const float eb[8] = { B0.x, B0.y, B0.z, B0.w, B1.x, B1.y, B1.z, B1.w };
                        float pa[8];
                        pa[0] = ea[0] * (z0 + h[0]);
                        #pragma unroll
                        for (int j = 1; j < 8; ++j) pa[j] = ea[j] * (h[j - 1] + h[j]);
                        float av[8];
                        float c = z1;
                        #pragma unroll
                        for (int j = 0; j < 8; ++j) { c = fmaf(ea[j], c, pa[j]); av[j] = c; }
                        float pb[8];
                        pb[0] = eb[0] * (z1 + av[0]);
                        #pragma unroll
                        for (int j = 1; j < 8; ++j) pb[j] = eb[j] * (av[j - 1] + av[j]);
                        const float o7n = h[7];
                        float d = z2;
                        #pragma unroll
                        for (int j = 0; j < 8; ++j) {
                            d = fmaf(eb[j], d, pb[j]);
                            h[j] = act ? d : h[j];
                        }
                        o7 = act ? o7n   : o7;
                        m7 = act ? av[7] : m7;
                        if (C == 0 && l == 31 && (unsigned)(s - 31) < (unsigned)NRP)
                            sts128v(mb + (unsigned)(((s - 31) & 63) * 16),
                                    o7, m7, h[7], __int_as_float(s - 31));
                    }
                }
            }
        }
        // joint rescale: publish local max, barrier, combine
        if ((t % 5) == 4) {
            float mx = fmaxf(o7, m7);
            #pragma unroll
            for (int j = 0; j < 8; ++j) mx = fmaxf(mx, h[j]);
            #pragma unroll
            for (int o = 16; o; o >>= 1)
                mx = fmaxf(mx, __shfl_xor_sync(FULL, mx, o));
            if (l == 0) jm[C] = mx;
        }
        __syncthreads();
        if ((t % 5) == 4) {
            const float mm = fmaxf(jm[0], jm[1]);
            if (mm > 0.f) {
                const int   k = (__float_as_int(mm) >> 23) - 127;
                const float f = __int_as_float((127 - k) << 23);
                #pragma unroll
                for (int j = 0; j < 8; ++j) h[j] *= f;
                o7 *= f; m7 *= f;
                Es += k;
                f_last = f;
            } else f_last = 1.f;
        }
    }
    // cell (511,511): consumer 1, lane 31, pair 255, row b -> h[7] at step 318
    if (C == 1 && l == 31)
        out[b] = -(logf(h[7]) + (float)Es * 0.69314718055994531f);
}

__global__ __launch_bounds__(160, 1)
void softdtw_fwd(const float* __restrict__ D, float* __restrict__ out) {
    extern __shared__ float sm[];
    __shared__ float4 mbox_s[64];
    __shared__ volatile float jm_s[2];

    const int b   = blockIdx.x;
    const int tid = threadIdx.x;
    const int w   = tid >> 5;
    const int l   = tid & 31;
    const float* __restrict__ Db = D + (size_t)b * NR * MC;
    const unsigned mb = (unsigned)__cvta_generic_to_shared(mbox_s);

    if (w < 3) {
        // ---------------- producers (warps 0,1,2) ----------------
        const float* G0 = Db + 8 * l;          // region0 cols 8l..
        const float* G1 = G0 + 256;            // region1 cols 256+8l..
        float* R0 = sm;
        float* R1 = sm + RS0 * SLOTW;

        auto load_blk = [&](const float* G, int k, float4* buf) {
            #pragma unroll
            for (int pp = 0; pp < 2; ++pp) {
                const int rp = 6 * k + 2 * w + pp;
                if (rp < NRP) {
                    const float* r0 = G + (size_t)(2 * rp) * MC;
                    const float4* s0 = (const float4*)r0;
                    const float4* s1 = (const float4*)(r0 + MC);
                    buf[pp * 4 + 0] = s0[0]; buf[pp * 4 + 1] = s0[1];
                    buf[pp * 4 + 2] = s1[0]; buf[pp * 4 + 3] = s1[1];
                }
            }
        };
        auto store_blk = [&](float* R, int RSc, int k, const float4* buf) {
            #pragma unroll
            for (int pp = 0; pp < 2; ++pp) {
                const int rp = 6 * k + 2 * w + pp;
                if (rp < NRP) {
                    const int slot = (rp + l) % RSc;
                    float4* dst = (float4*)(R + slot * SLOTW + l * LS);
                    dst[0] = exp4neg(buf[pp * 4 + 0]);
                    dst[1] = exp4neg(buf[pp * 4 + 1]);
                    dst[2] = exp4neg(buf[pp * 4 + 2]);
                    dst[3] = exp4neg(buf[pp * 4 + 3]);
                }
            }
        };

        {   // prologue: region0 block 0 before first barrier
            float4 T[8];
            load_blk(G0, 0, T);
            store_blk(R0, RS0, 0, T);
        }
        float4 X0[8], Y0[8], Z1a[8], Z1b[8];
        load_blk(G0, 1, X0);

        for (int t = 0; t + 1 < NPHASE; t += 2) {
            // phase t (even)
            __syncthreads();
            if (t + 2 <= 42) load_blk(G0, t + 2, Y0);
            if (t + 1 <= 42) store_blk(R0, RS0, t + 1, X0);
            if (t - 4 >= 0 && t - 4 <= 42) store_blk(R1, RS1, t - 4, Z1a);
            if (t - 2 >= 0 && t - 2 <= 42) load_blk(G1, t - 2, Z1a);
            __syncthreads();
            // phase t+1 (odd)
            __syncthreads();
            if (t + 3 <= 42) load_blk(G0, t + 3, X0);
            if (t + 2 <= 42) store_blk(R0, RS0, t + 2, Y0);
            if (t - 3 >= 0 && t - 3 <= 42) store_blk(R1, RS1, t - 3, Z1b);
            if (t - 1 >= 0 && t - 1 <= 42) load_blk(G1, t - 1, Z1b);
            __syncthreads();
        }
    } else if (w == 3) {
        // init mailbox tags before first barrier
        #pragma unroll
        for (int i = 0; i < 2; ++i)
            sts128v(mb + (unsigned)((l + 32 * i) * 16), 0.f, 0.f, 0.f,
                    __int_as_float(-1));
        consumer_loop<0>(sm, out, b, l, mb, jm_s);
    } else {
        consumer_loop<1>(sm + RS0 * SLOTW, out, b, l, mb, jm_s);
    }
}

extern "C" void kernel_launch(void* const* d_in, const int* in_sizes, int n_in,
                              void* d_out, int out_size) {
    (void)in_sizes; (void)n_in; (void)out_size;
    const float* D = (const float*)d_in[0];
    float* o       = (float*)d_out;
    cudaFuncSetAttribute(softdtw_fwd, cudaFuncAttributeMaxDynamicSharedMemorySize, SMEM_BYTES);
    softdtw_fwd<<<BATCH, 160, SMEM_BYTES>>>(D, o);
}